// round 17
// baseline (speedup 1.0000x reference)
#include <cuda_runtime.h>
#include <cuda_fp16.h>
#include <cuda_bf16.h>
#include <cstdint>
#include <cfloat>
#include <math.h>

#define B_   32
#define T_   512
#define DIN  1024
#define DCB  256
#define KCB  8192
#define HMID 512
#define M_   (B_*T_)   // 16384
#define K3   (3*DCB)   // 768

typedef unsigned long long ull;
typedef unsigned int uint32;

// ---------------- scratch ------------------------------------------------------
__device__ float g_Y1[M_*HMID];
__device__ float g_Y2[M_*DCB];
__device__ float g_W1t[DIN*HMID];
__device__ float g_W2t[HMID*DCB];
__device__ float g_Wct[K3*DCB];
__device__ float g_feat[M_*DCB];
__device__ float g_cnorm[KCB];
__device__ float g_rownorm[M_];
__device__ float g_absF[M_];
__device__ float g_SF[M_];
__device__ float g_absC[KCB];
__device__ float g_absQ[M_];
__device__ float g_absW[K3];
__device__ uint32 g_maxAbsC_bits;
__device__ uint32 g_maxSC_bits;
__device__ int   g_FiT[64*M_];
__device__ int   g_CBiT[64*KCB];
__device__ int   g_QiT[64*M_];
__device__ int   g_Wih8T[64*K3];
__device__ int   g_whh8p[64*K3];
__device__ float g_whhScale[K3];
__device__ __nv_bfloat16 g_scores[(size_t)M_*KCB];
__device__ float g_bmin[(size_t)M_*64];
__device__ ull   g_bestkey[M_];
__device__ int   g_idx[M_];
__device__ float g_xproj[M_*K3];
__device__ float g_accum[2];

__device__ __forceinline__ uint32 ford(float f) {
    uint32 b = __float_as_uint(f);
    return (b & 0x80000000u) ? ~b : (b | 0x80000000u);
}

// cp.async helpers
__device__ __forceinline__ void cp16(void* smem, const void* g) {
    uint32 s = (uint32)__cvta_generic_to_shared(smem);
    asm volatile("cp.async.ca.shared.global [%0], [%1], 16;\n" :: "r"(s), "l"(g));
}
__device__ __forceinline__ void cp16z(void* smem, const void* g, bool ok) {
    uint32 s = (uint32)__cvta_generic_to_shared(smem);
    int sz = ok ? 16 : 0;
    asm volatile("cp.async.ca.shared.global [%0], [%1], 16, %2;\n"
                 :: "r"(s), "l"(g), "r"(sz));
}
#define CP_COMMIT()  asm volatile("cp.async.commit_group;\n" ::: "memory")
#define CP_WAIT(n)   asm volatile("cp.async.wait_group %0;\n" :: "n"(n) : "memory")

// ---------------- fp32 SIMT GEMM, 2-stage cp.async (round-15 proven) ------------
#define BM 128
#define BN 128
#define BKK 16

template<int RELU>
__global__ __launch_bounds__(256, 2) void gemm_tn(
    const float* __restrict__ A, const float* __restrict__ Bt,
    const float* __restrict__ bias, float* __restrict__ C,
    int M, int N, int K)
{
    __shared__ float As[2][BM][BKK];
    __shared__ float Bs[2][BKK][BN];
    int tid = threadIdx.x;
    int tr = tid >> 4, tc = tid & 15;
    int m0 = blockIdx.y * BM, n0 = blockIdx.x * BN;
    float acc[8][8];
    #pragma unroll
    for (int i = 0; i < 8; i++)
        #pragma unroll
        for (int j = 0; j < 8; j++) acc[i][j] = 0.f;

    int arow0 = tid >> 2,          aq0 = (tid & 3) << 2;
    int arow1 = (tid + 256) >> 2,  aq1 = aq0;
    int brow0 = tid >> 5,          bc0 = (tid & 31) << 2;
    int brow1 = (tid + 256) >> 5,  bc1 = bc0;

    int Ttiles = K / BKK;
    {
        cp16(&As[0][arow0][aq0], &A[(size_t)(m0+arow0)*K + aq0]);
        cp16(&As[0][arow1][aq1], &A[(size_t)(m0+arow1)*K + aq1]);
        cp16(&Bs[0][brow0][bc0], &Bt[(size_t)brow0*N + n0 + bc0]);
        cp16(&Bs[0][brow1][bc1], &Bt[(size_t)brow1*N + n0 + bc1]);
        CP_COMMIT();
    }
    for (int t = 0; t < Ttiles; t++) {
        int cur = t & 1;
        if (t + 1 < Ttiles) {
            int k0 = (t+1) * BKK;
            int nxt = cur ^ 1;
            cp16(&As[nxt][arow0][aq0], &A[(size_t)(m0+arow0)*K + k0 + aq0]);
            cp16(&As[nxt][arow1][aq1], &A[(size_t)(m0+arow1)*K + k0 + aq1]);
            cp16(&Bs[nxt][brow0][bc0], &Bt[(size_t)(k0+brow0)*N + n0 + bc0]);
            cp16(&Bs[nxt][brow1][bc1], &Bt[(size_t)(k0+brow1)*N + n0 + bc1]);
            CP_COMMIT();
            CP_WAIT(1);
        } else {
            CP_WAIT(0);
        }
        __syncthreads();
        #pragma unroll
        for (int kq4 = 0; kq4 < 4; kq4++) {
            float4 bL[4], bH[4];
            #pragma unroll
            for (int kk2 = 0; kk2 < 4; kk2++) {
                bL[kk2] = *(const float4*)&Bs[cur][kq4*4+kk2][tc*4];
                bH[kk2] = *(const float4*)&Bs[cur][kq4*4+kk2][64 + tc*4];
            }
            #pragma unroll
            for (int i = 0; i < 8; i++) {
                float4 a4 = *(const float4*)&As[cur][tr*8+i][kq4*4];
                float av[4] = {a4.x, a4.y, a4.z, a4.w};
                #pragma unroll
                for (int kk2 = 0; kk2 < 4; kk2++) {
                    float a = av[kk2];
                    acc[i][0] = __fmaf_rn(a, bL[kk2].x, acc[i][0]);
                    acc[i][1] = __fmaf_rn(a, bL[kk2].y, acc[i][1]);
                    acc[i][2] = __fmaf_rn(a, bL[kk2].z, acc[i][2]);
                    acc[i][3] = __fmaf_rn(a, bL[kk2].w, acc[i][3]);
                    acc[i][4] = __fmaf_rn(a, bH[kk2].x, acc[i][4]);
                    acc[i][5] = __fmaf_rn(a, bH[kk2].y, acc[i][5]);
                    acc[i][6] = __fmaf_rn(a, bH[kk2].z, acc[i][6]);
                    acc[i][7] = __fmaf_rn(a, bH[kk2].w, acc[i][7]);
                }
            }
        }
        __syncthreads();
    }
    float4 bvA = *(const float4*)&bias[n0 + tc*4];
    float4 bvB = *(const float4*)&bias[n0 + 64 + tc*4];
    float bbA[4] = {bvA.x,bvA.y,bvA.z,bvA.w};
    float bbB[4] = {bvB.x,bvB.y,bvB.z,bvB.w};
    #pragma unroll
    for (int i = 0; i < 8; i++) {
        int m = m0 + tr*8 + i;
        float oA[4], oB[4];
        #pragma unroll
        for (int j = 0; j < 4; j++) {
            float vA = __fadd_rn(acc[i][j],   bbA[j]);
            float vB = __fadd_rn(acc[i][4+j], bbB[j]);
            if (RELU) { vA = fmaxf(vA, 0.f); vB = fmaxf(vB, 0.f); }
            oA[j] = vA; oB[j] = vB;
        }
        *(float4*)&C[(size_t)m*N + n0 + tc*4]      = make_float4(oA[0],oA[1],oA[2],oA[3]);
        *(float4*)&C[(size_t)m*N + n0 + 64 + tc*4] = make_float4(oB[0],oB[1],oB[2],oB[3]);
    }
}

// ---------------- conv GEMM with fused im2col, 2-stage (round-15 proven) --------
__global__ __launch_bounds__(256, 2) void gemm_conv(
    const float* __restrict__ Y2, const float* __restrict__ Bt,
    const float* __restrict__ bias, float* __restrict__ C)
{
    const int N = DCB, K = K3;
    __shared__ float As[2][BM][BKK];
    __shared__ float Bs[2][BKK][BN];
    int tid = threadIdx.x;
    int tr = tid >> 4, tc = tid & 15;
    int m0 = blockIdx.y * BM, n0 = blockIdx.x * BN;
    float acc[8][8];
    #pragma unroll
    for (int i = 0; i < 8; i++)
        #pragma unroll
        for (int j = 0; j < 8; j++) acc[i][j] = 0.f;

    int arow0 = tid >> 2,          aq0 = (tid & 3) << 2;
    int arow1 = (tid + 256) >> 2,  aq1 = aq0;
    int brow0 = tid >> 5,          bc0 = (tid & 31) << 2;
    int brow1 = (tid + 256) >> 5,  bc1 = bc0;

    int mA0 = m0 + arow0, bA0 = mA0 >> 9, tA0 = mA0 & 511;
    int mA1 = m0 + arow1, bA1 = mA1 >> 9, tA1 = mA1 & 511;

    auto stageA = [&](int buf, int k0) {
        int gk0 = k0 + aq0;
        int tap0 = gk0 >> 8, i0 = gk0 & 255;
        int tt0 = tA0 + tap0 - 1;
        bool ok0 = (unsigned)tt0 < 512u;
        cp16z(&As[buf][arow0][aq0],
              &Y2[((size_t)(bA0 << 9) + (ok0 ? tt0 : 0))*DCB + i0], ok0);
        int gk1 = k0 + aq1;
        int tap1 = gk1 >> 8, i1 = gk1 & 255;
        int tt1 = tA1 + tap1 - 1;
        bool ok1 = (unsigned)tt1 < 512u;
        cp16z(&As[buf][arow1][aq1],
              &Y2[((size_t)(bA1 << 9) + (ok1 ? tt1 : 0))*DCB + i1], ok1);
    };

    int Ttiles = K / BKK;
    {
        stageA(0, 0);
        cp16(&Bs[0][brow0][bc0], &Bt[(size_t)brow0*N + n0 + bc0]);
        cp16(&Bs[0][brow1][bc1], &Bt[(size_t)brow1*N + n0 + bc1]);
        CP_COMMIT();
    }
    for (int t = 0; t < Ttiles; t++) {
        int cur = t & 1;
        if (t + 1 < Ttiles) {
            int k0 = (t+1) * BKK;
            int nxt = cur ^ 1;
            stageA(nxt, k0);
            cp16(&Bs[nxt][brow0][bc0], &Bt[(size_t)(k0+brow0)*N + n0 + bc0]);
            cp16(&Bs[nxt][brow1][bc1], &Bt[(size_t)(k0+brow1)*N + n0 + bc1]);
            CP_COMMIT();
            CP_WAIT(1);
        } else {
            CP_WAIT(0);
        }
        __syncthreads();
        #pragma unroll
        for (int kq4 = 0; kq4 < 4; kq4++) {
            float4 bL[4], bH[4];
            #pragma unroll
            for (int kk2 = 0; kk2 < 4; kk2++) {
                bL[kk2] = *(const float4*)&Bs[cur][kq4*4+kk2][tc*4];
                bH[kk2] = *(const float4*)&Bs[cur][kq4*4+kk2][64 + tc*4];
            }
            #pragma unroll
            for (int i = 0; i < 8; i++) {
                float4 a4 = *(const float4*)&As[cur][tr*8+i][kq4*4];
                float av[4] = {a4.x, a4.y, a4.z, a4.w};
                #pragma unroll
                for (int kk2 = 0; kk2 < 4; kk2++) {
                    float a = av[kk2];
                    acc[i][0] = __fmaf_rn(a, bL[kk2].x, acc[i][0]);
                    acc[i][1] = __fmaf_rn(a, bL[kk2].y, acc[i][1]);
                    acc[i][2] = __fmaf_rn(a, bL[kk2].z, acc[i][2]);
                    acc[i][3] = __fmaf_rn(a, bL[kk2].w, acc[i][3]);
                    acc[i][4] = __fmaf_rn(a, bH[kk2].x, acc[i][4]);
                    acc[i][5] = __fmaf_rn(a, bH[kk2].y, acc[i][5]);
                    acc[i][6] = __fmaf_rn(a, bH[kk2].z, acc[i][6]);
                    acc[i][7] = __fmaf_rn(a, bH[kk2].w, acc[i][7]);
                }
            }
        }
        __syncthreads();
    }
    float4 bvA = *(const float4*)&bias[n0 + tc*4];
    float4 bvB = *(const float4*)&bias[n0 + 64 + tc*4];
    float bbA[4] = {bvA.x,bvA.y,bvA.z,bvA.w};
    float bbB[4] = {bvB.x,bvB.y,bvB.z,bvB.w};
    #pragma unroll
    for (int i = 0; i < 8; i++) {
        int m = m0 + tr*8 + i;
        float oA[4], oB[4];
        #pragma unroll
        for (int j = 0; j < 4; j++) {
            oA[j] = __fadd_rn(acc[i][j],   bbA[j]);
            oB[j] = __fadd_rn(acc[i][4+j], bbB[j]);
        }
        *(float4*)&C[(size_t)m*N + n0 + tc*4]      = make_float4(oA[0],oA[1],oA[2],oA[3]);
        *(float4*)&C[(size_t)m*N + n0 + 64 + tc*4] = make_float4(oB[0],oB[1],oB[2],oB[3]);
    }
}

// ---------------- transposes ---------------------------------------------------
__global__ void transpose_f(const float* __restrict__ in, float* __restrict__ out,
                            int R, int C) {
    __shared__ float t[32][33];
    int bx = blockIdx.x*32, by = blockIdx.y*32;
    int tx = threadIdx.x, ty = threadIdx.y;
    #pragma unroll
    for (int dy = 0; dy < 32; dy += 8)
        t[ty+dy][tx] = in[(size_t)(by+ty+dy)*C + bx+tx];
    __syncthreads();
    #pragma unroll
    for (int dy = 0; dy < 32; dy += 8)
        out[(size_t)(bx+ty+dy)*R + by+tx] = t[tx][ty+dy];
}

// ---------------- small prep kernels ------------------------------------------
__global__ void init_misc() {
    int i = blockIdx.x*blockDim.x + threadIdx.x;
    if (i < 2) g_accum[i] = 0.f;
    if (i == 0) { g_maxAbsC_bits = 0; g_maxSC_bits = 0; }
    if (i < M_) g_bestkey[i] = 0xFFFFFFFFFFFFFFFFull;
}

__global__ void prep_wct(const float* __restrict__ conv_w) {
    int o = blockIdx.x*blockDim.x + threadIdx.x;
    if (o >= K3*DCB) return;
    int r = o / DCB, c = o % DCB, k = r / DCB, i = r % DCB;
    g_Wct[o] = conv_w[((size_t)c*DCB + i)*3 + k];
}

__global__ void whh_quant(const float* __restrict__ whh) {
    int j = blockIdx.x;
    int tid = threadIdx.x;
    const float* row = whh + (size_t)j*DCB;
    float v = fabsf(row[tid]);
    #pragma unroll
    for (int off = 16; off; off >>= 1) v = fmaxf(v, __shfl_xor_sync(0xffffffffu, v, off));
    __shared__ float red[8];
    __shared__ float smax;
    if ((tid & 31) == 0) red[tid >> 5] = v;
    __syncthreads();
    if (tid == 0) {
        float m = red[0];
        #pragma unroll
        for (int w = 1; w < 8; w++) m = fmaxf(m, red[w]);
        smax = m;
        g_whhScale[j] = m / (127.f*127.f);
    }
    __syncthreads();
    if (tid < 64) {
        float s = smax > 0.f ? 127.f/smax : 0.f;
        int d = tid*4;
        int b0 = max(-127, min(127, __float2int_rn(row[d+0]*s)));
        int b1 = max(-127, min(127, __float2int_rn(row[d+1]*s)));
        int b2 = max(-127, min(127, __float2int_rn(row[d+2]*s)));
        int b3 = max(-127, min(127, __float2int_rn(row[d+3]*s)));
        g_whh8p[tid*K3 + j] = (b0 & 255) | ((b1 & 255) << 8) |
                              ((b2 & 255) << 16) | ((b3 & 255) << 24);
    }
}

__global__ void absmax_rows(const float* __restrict__ src, float* __restrict__ out) {
    int r = blockIdx.x;
    int tid = threadIdx.x;
    float v = fabsf(src[(size_t)r*DCB + tid]);
    #pragma unroll
    for (int off = 16; off; off >>= 1) v = fmaxf(v, __shfl_xor_sync(0xffffffffu, v, off));
    __shared__ float red[8];
    if ((tid & 31) == 0) red[tid >> 5] = v;
    __syncthreads();
    if (tid == 0) {
        float m = red[0];
        #pragma unroll
        for (int w = 1; w < 8; w++) m = fmaxf(m, red[w]);
        out[r] = m;
    }
}

__global__ void cnorm_k(const float* __restrict__ CB) {
    int k = blockIdx.x*blockDim.x + threadIdx.x;
    if (k >= KCB) return;
    const float* row = CB + (size_t)k*DCB;
    float a = 0.f, mx = 0.f, sab = 0.f;
    for (int d = 0; d < DCB; d++) {
        float v = row[d];
        a = __fadd_rn(a, __fmul_rn(v, v));
        float av = fabsf(v);
        mx = fmaxf(mx, av);
        sab += av;
    }
    g_cnorm[k] = a;
    g_absC[k] = mx;
    atomicMax(&g_maxAbsC_bits, __float_as_uint(mx));
    atomicMax(&g_maxSC_bits, __float_as_uint(sab));
}

__global__ void rownorm_k() {
    int m = blockIdx.x*blockDim.x + threadIdx.x;
    if (m >= M_) return;
    const float* row = g_feat + (size_t)m*DCB;
    float a = 0.f, mx = 0.f, sab = 0.f;
    for (int d = 0; d < DCB; d++) {
        float v = row[d];
        a = __fadd_rn(a, __fmul_rn(v, v));
        float av = fabsf(v);
        mx = fmaxf(mx, av);
        sab += av;
    }
    g_rownorm[m] = a;
    g_absF[m] = mx;
    g_SF[m] = sab;
}

__global__ void quant_pack(const float* __restrict__ src,
                           const float* __restrict__ absArr,
                           int* __restrict__ out, int R)
{
    __shared__ float tile[32][DCB];
    __shared__ float sc[32];
    int r0 = blockIdx.x * 32;
    int tid = threadIdx.x;
    #pragma unroll
    for (int p = 0; p < 32; p++) {
        int id = tid + p*256;
        int r = id >> 8, c = id & 255;
        tile[r][c] = src[(size_t)(r0+r)*DCB + c];
    }
    if (tid < 32) {
        float a = absArr[r0+tid];
        sc[tid] = a > 0.f ? 127.f/a : 0.f;
    }
    __syncthreads();
    int ml = tid & 31;
    int k4b = tid >> 5;
    float s = sc[ml];
    #pragma unroll
    for (int p = 0; p < 8; p++) {
        int k4 = k4b + p*8;
        int d = k4*4;
        int b0 = max(-127, min(127, __float2int_rn(tile[ml][d+0]*s)));
        int b1 = max(-127, min(127, __float2int_rn(tile[ml][d+1]*s)));
        int b2 = max(-127, min(127, __float2int_rn(tile[ml][d+2]*s)));
        int b3 = max(-127, min(127, __float2int_rn(tile[ml][d+3]*s)));
        out[(size_t)k4*R + r0 + ml] = (b0 & 255) | ((b1 & 255) << 8) |
                                      ((b2 & 255) << 16) | ((b3 & 255) << 24);
    }
}

// ---------------- VQ: int8 dp4a GEMM -> bf16 scores + per-block row mins --------
__global__ __launch_bounds__(256, 2) void vq_i8()
{
    __shared__ int As[2][16][128];
    __shared__ int Bs[2][16][128];
    int tid = threadIdx.x;
    int tr = tid >> 4, tc = tid & 15;
    int m0 = blockIdx.x * 128;
    int n0 = blockIdx.y * 128;

    int acc[8][8];
    #pragma unroll
    for (int i = 0; i < 8; i++)
        #pragma unroll
        for (int j = 0; j < 8; j++) acc[i][j] = 0;

    int row0 = tid >> 5,          c0 = (tid & 31);
    int row1 = (tid + 256) >> 5,  c1 = c0;

    cp16(&As[0][row0][c0*4], &g_FiT[(size_t)row0*M_ + m0 + c0*4]);
    cp16(&As[0][row1][c1*4], &g_FiT[(size_t)row1*M_ + m0 + c1*4]);
    cp16(&Bs[0][row0][c0*4], &g_CBiT[(size_t)row0*KCB + n0 + c0*4]);
    cp16(&Bs[0][row1][c1*4], &g_CBiT[(size_t)row1*KCB + n0 + c1*4]);
    CP_COMMIT();

    for (int ch = 0; ch < 4; ch++) {
        int cur = ch & 1;
        if (ch + 1 < 4) {
            int k40 = (ch+1)*16;
            int nxt = cur ^ 1;
            cp16(&As[nxt][row0][c0*4], &g_FiT[(size_t)(k40+row0)*M_ + m0 + c0*4]);
            cp16(&As[nxt][row1][c1*4], &g_FiT[(size_t)(k40+row1)*M_ + m0 + c1*4]);
            cp16(&Bs[nxt][row0][c0*4], &g_CBiT[(size_t)(k40+row0)*KCB + n0 + c0*4]);
            cp16(&Bs[nxt][row1][c1*4], &g_CBiT[(size_t)(k40+row1)*KCB + n0 + c1*4]);
            CP_COMMIT();
            CP_WAIT(1);
        } else {
            CP_WAIT(0);
        }
        __syncthreads();
        #pragma unroll
        for (int kk = 0; kk < 16; kk++) {
            int4 a0 = *(const int4*)&As[cur][kk][tr*8];
            int4 a1 = *(const int4*)&As[cur][kk][tr*8+4];
            int4 b0 = *(const int4*)&Bs[cur][kk][tc*8];
            int4 b1 = *(const int4*)&Bs[cur][kk][tc*8+4];
            int av[8] = {a0.x,a0.y,a0.z,a0.w,a1.x,a1.y,a1.z,a1.w};
            int bv[8] = {b0.x,b0.y,b0.z,b0.w,b1.x,b1.y,b1.z,b1.w};
            #pragma unroll
            for (int i = 0; i < 8; i++)
                #pragma unroll
                for (int j = 0; j < 8; j++)
                    acc[i][j] = __dp4a(av[i], bv[j], acc[i][j]);
        }
        __syncthreads();
    }

    const float inv127 = 1.f/127.f;
    float sC[8], cnv[8];
    #pragma unroll
    for (int j = 0; j < 8; j++) {
        int n = n0 + tc*8 + j;
        sC[j] = g_absC[n] * inv127;
        cnv[j] = g_cnorm[n];
    }
    #pragma unroll
    for (int i = 0; i < 8; i++) {
        int m = m0 + tr*8 + i;
        float sF = g_absF[m] * inv127;
        __nv_bfloat16 hb[8];
        float mn = FLT_MAX;
        #pragma unroll
        for (int j = 0; j < 8; j++) {
            float s = cnv[j] - 2.f*((float)acc[i][j] * (sF * sC[j]));
            hb[j] = __float2bfloat16_rn(s);
            mn = fminf(mn, s);
        }
        *(uint4*)&g_scores[(size_t)m*KCB + n0 + tc*8] = *(uint4*)hb;
        #pragma unroll
        for (int off = 1; off < 16; off <<= 1)
            mn = fminf(mn, __shfl_xor_sync(0xffffffffu, mn, off));
        if (tc == 0) g_bmin[(size_t)m*64 + blockIdx.y] = mn;
    }
}

// ---------------- xproj: int8 dp4a GEMM (round-16 proven) -----------------------
__global__ __launch_bounds__(256, 2) void xproj_i8(const float* __restrict__ bih)
{
    __shared__ int As[2][16][128];
    __shared__ int Bs[2][16][128];
    int tid = threadIdx.x;
    int tr = tid >> 4, tc = tid & 15;
    int m0 = blockIdx.x * 128;
    int n0 = blockIdx.y * 128;

    int acc[8][8];
    #pragma unroll
    for (int i = 0; i < 8; i++)
        #pragma unroll
        for (int j = 0; j < 8; j++) acc[i][j] = 0;

    int row0 = tid >> 5,          c0 = (tid & 31);
    int row1 = (tid + 256) >> 5,  c1 = c0;

    cp16(&As[0][row0][c0*4], &g_QiT[(size_t)row0*M_ + m0 + c0*4]);
    cp16(&As[0][row1][c1*4], &g_QiT[(size_t)row1*M_ + m0 + c1*4]);
    cp16(&Bs[0][row0][c0*4], &g_Wih8T[(size_t)row0*K3 + n0 + c0*4]);
    cp16(&Bs[0][row1][c1*4], &g_Wih8T[(size_t)row1*K3 + n0 + c1*4]);
    CP_COMMIT();

    for (int ch = 0; ch < 4; ch++) {
        int cur = ch & 1;
        if (ch + 1 < 4) {
            int k40 = (ch+1)*16;
            int nxt = cur ^ 1;
            cp16(&As[nxt][row0][c0*4], &g_QiT[(size_t)(k40+row0)*M_ + m0 + c0*4]);
            cp16(&As[nxt][row1][c1*4], &g_QiT[(size_t)(k40+row1)*M_ + m0 + c1*4]);
            cp16(&Bs[nxt][row0][c0*4], &g_Wih8T[(size_t)(k40+row0)*K3 + n0 + c0*4]);
            cp16(&Bs[nxt][row1][c1*4], &g_Wih8T[(size_t)(k40+row1)*K3 + n0 + c1*4]);
            CP_COMMIT();
            CP_WAIT(1);
        } else {
            CP_WAIT(0);
        }
        __syncthreads();
        #pragma unroll
        for (int kk = 0; kk < 16; kk++) {
            int4 a0 = *(const int4*)&As[cur][kk][tr*8];
            int4 a1 = *(const int4*)&As[cur][kk][tr*8+4];
            int4 b0 = *(const int4*)&Bs[cur][kk][tc*8];
            int4 b1 = *(const int4*)&Bs[cur][kk][tc*8+4];
            int av[8] = {a0.x,a0.y,a0.z,a0.w,a1.x,a1.y,a1.z,a1.w};
            int bv[8] = {b0.x,b0.y,b0.z,b0.w,b1.x,b1.y,b1.z,b1.w};
            #pragma unroll
            for (int i = 0; i < 8; i++)
                #pragma unroll
                for (int j = 0; j < 8; j++)
                    acc[i][j] = __dp4a(av[i], bv[j], acc[i][j]);
        }
        __syncthreads();
    }

    const float inv127 = 1.f/127.f;
    float sW[8], bb[8];
    #pragma unroll
    for (int j = 0; j < 8; j++) {
        int n = n0 + tc*8 + j;
        sW[j] = g_absW[n] * inv127;
        bb[j] = bih[n];
    }
    #pragma unroll
    for (int i = 0; i < 8; i++) {
        int m = m0 + tr*8 + i;
        float sQ = g_absQ[m] * inv127;
        float o[8];
        #pragma unroll
        for (int j = 0; j < 8; j++)
            o[j] = (float)acc[i][j] * (sQ * sW[j]) + bb[j];
        *(float4*)&g_xproj[(size_t)m*K3 + n0 + tc*8]     = make_float4(o[0],o[1],o[2],o[3]);
        *(float4*)&g_xproj[(size_t)m*K3 + n0 + tc*8 + 4] = make_float4(o[4],o[5],o[6],o[7]);
    }
}

// ---------------- VQ rescue: warp-per-row with block-min skipping ---------------
// One warp handles one feature row: reduce 64 block-mins -> rowmin/thr, then scan
// only blocks with bmin <= thr (typically 1-3). Exact rescore chain unchanged.
__global__ __launch_bounds__(256) void vq_rescue(const float* __restrict__ CBfp)
{
    int w = threadIdx.x >> 5, lane = threadIdx.x & 31;
    int m = blockIdx.x*8 + w;
    float b0 = g_bmin[(size_t)m*64 + lane];
    float b1 = g_bmin[(size_t)m*64 + 32 + lane];
    float mn = fminf(b0, b1);
    #pragma unroll
    for (int off = 16; off; off >>= 1)
        mn = fminf(mn, __shfl_xor_sync(0xffffffffu, mn, off));

    float maxAbsC = __uint_as_float(g_maxAbsC_bits);
    float maxSC   = __uint_as_float(g_maxSC_bits);
    float errP = (g_absF[m]*maxSC + maxAbsC*g_SF[m]) * (1.f/254.f);
    float thr = mn + 4.f*errP + 1.2e-5f;
    float A = g_rownorm[m];
    const float* fr = g_feat + (size_t)m*DCB;
    const __nv_bfloat16* srow = g_scores + (size_t)m*KCB;

    for (int by = 0; by < 64; by++) {
        float bm = (by < 32) ? __shfl_sync(0xffffffffu, b0, by)
                             : __shfl_sync(0xffffffffu, b1, by-32);
        if (bm > thr) continue;
        uint2 pk = *(const uint2*)&srow[by*128 + lane*4];
        __nv_bfloat16 hv[4];
        *(uint2*)hv = pk;
        #pragma unroll
        for (int e = 0; e < 4; e++) {
            float s = __bfloat162float(hv[e]);
            if (s <= thr) {
                int n = by*128 + lane*4 + e;
                const float* cr = CBfp + (size_t)n*DCB;
                float p = 0.f;
                #pragma unroll 8
                for (int k = 0; k < DCB; k++)
                    p = __fmaf_rn(fr[k], cr[k], p);
                float se = __fadd_rn(__fadd_rn(A, -__fmul_rn(2.f, p)), g_cnorm[n]);
                ull key = ((ull)ford(se) << 32) | (uint32)n;
                atomicMin(&g_bestkey[m], key);
            }
        }
    }
}

// fused: extract idx -> out + absQ, gather quantized -> out, accumulate MSE
__global__ void vq_extract_mse(const float* __restrict__ CB, float* __restrict__ out) {
    int m = blockIdx.x, c = threadIdx.x;
    int id = (int)(g_bestkey[m] & 0xFFFFFFFFull);
    if (c == 0) {
        g_idx[m] = id;
        out[m] = (float)id;
        g_absQ[m] = g_absC[id];
    }
    float q = CB[(size_t)id*DCB + c];
    out[M_ + (size_t)m*DCB + c] = q;
    float d = g_feat[(size_t)m*DCB + c] - q;
    float s = d*d;
    #pragma unroll
    for (int off = 16; off; off >>= 1) s += __shfl_down_sync(0xffffffffu, s, off);
    __shared__ float red[8];
    if ((c & 31) == 0) red[c >> 5] = s;
    __syncthreads();
    if (c == 0) {
        float tt = 0.f;
        #pragma unroll
        for (int w = 0; w < 8; w++) tt += red[w];
        atomicAdd(&g_accum[0], tt);
    }
}

// ---------------- GRU: int8 weights in smem, dp4a (round-14 proven) -------------
__global__ __launch_bounds__(768) void gru_kernel(const float* __restrict__ bhh) {
    extern __shared__ int wsm[];
    __shared__ signed char sh_h8[DCB];
    __shared__ float sh_gh[K3];
    __shared__ int parti[4][K3];
    __shared__ float wsum[24];
    int b = blockIdx.x;
    int tid = threadIdx.x;
    int ds = tid / 192;
    int jj = tid % 192;

    for (int i = tid; i < 64*K3/4; i += 768)
        ((int4*)wsm)[i] = ((const int4*)g_whh8p)[i];
    if (tid < DCB) sh_h8[tid] = 0;
    float bhv = bhh[tid];
    float cscale = g_whhScale[tid];
    float hprev = 0.f;
    float ctxsum = 0.f;
    __syncthreads();

    const int* h8w = (const int*)sh_h8;
    for (int t = 0; t < T_-1; t++) {
        int hp[16];
        #pragma unroll
        for (int q4 = 0; q4 < 4; q4++) {
            int4 v = ((const int4*)h8w)[ds*4 + q4];
            hp[q4*4+0] = v.x; hp[q4*4+1] = v.y; hp[q4*4+2] = v.z; hp[q4*4+3] = v.w;
        }
        #pragma unroll
        for (int q = 0; q < 4; q++) {
            int j = jj + q*192;
            int acc = 0;
            #pragma unroll
            for (int d4i = 0; d4i < 16; d4i++)
                acc = __dp4a(hp[d4i], wsm[(ds*16 + d4i)*K3 + j], acc);
            parti[ds][j] = acc;
        }
        __syncthreads();
        sh_gh[tid] = (float)(parti[0][tid] + parti[1][tid] + parti[2][tid]
                           + parti[3][tid]) * cscale + bhv;
        __syncthreads();
        if (tid < DCB) {
            int j = tid;
            const float* xp = g_xproj + ((size_t)b*T_ + t)*K3;
            float r = 1.f/(1.f + expf(-(xp[j]       + sh_gh[j])));
            float z = 1.f/(1.f + expf(-(xp[DCB+j]   + sh_gh[DCB+j])));
            float n = tanhf(xp[2*DCB+j] + r*sh_gh[2*DCB+j]);
            float hnew = (1.f - z)*n + z*hprev;
            float dl = hnew - g_feat[((size_t)b*T_ + t + 1)*DCB + j];
            ctxsum = fmaf(dl, dl, ctxsum);
            hprev = hnew;
            float hq = fminf(fmaxf(hnew*127.f, -127.f), 127.f);
            sh_h8[j] = (signed char)__float2int_rn(hq);
        }
        __syncthreads();
    }
    #pragma unroll
    for (int off = 16; off; off >>= 1) ctxsum += __shfl_down_sync(0xffffffffu, ctxsum, off);
    if ((tid & 31) == 0) wsum[tid >> 5] = ctxsum;
    __syncthreads();
    if (tid == 0) {
        float s = 0.f;
        #pragma unroll
        for (int w = 0; w < 24; w++) s += wsum[w];
        atomicAdd(&g_accum[1], s);
    }
}

__global__ void finalize_k(float* __restrict__ out) {
    float mse = g_accum[0] / 4194304.0f;
    float ctx = g_accum[1] / 4186112.0f;
    size_t base = (size_t)M_ + (size_t)M_*DCB;
    out[base+0] = mse;
    out[base+1] = mse;
    out[base+2] = ctx;
    out[base+3] = 1.25f*mse + 0.1f*ctx;
}

// ---------------- launch --------------------------------------------------------
extern "C" void kernel_launch(void* const* d_in, const int* in_sizes, int n_in,
                              void* d_out, int out_size) {
    const float* x      = (const float*)d_in[0];
    const float* w1     = (const float*)d_in[1];
    const float* b1     = (const float*)d_in[2];
    const float* w2     = (const float*)d_in[3];
    const float* b2     = (const float*)d_in[4];
    const float* conv_w = (const float*)d_in[5];
    const float* conv_b = (const float*)d_in[6];
    const float* cb     = (const float*)d_in[7];
    const float* wih    = (const float*)d_in[8];
    const float* whh    = (const float*)d_in[9];
    const float* bih    = (const float*)d_in[10];
    const float* bhh    = (const float*)d_in[11];
    float* out = (float*)d_out;

    float *pY1, *pY2, *pW1t, *pW2t, *pWct, *pF;
    float *pAbsF, *pAbsC, *pAbsQ, *pAbsW;
    int *pFiT, *pCBiT, *pQiT, *pWih8T;
    cudaGetSymbolAddress((void**)&pY1, g_Y1);
    cudaGetSymbolAddress((void**)&pY2, g_Y2);
    cudaGetSymbolAddress((void**)&pW1t, g_W1t);
    cudaGetSymbolAddress((void**)&pW2t, g_W2t);
    cudaGetSymbolAddress((void**)&pWct, g_Wct);
    cudaGetSymbolAddress((void**)&pF,  g_feat);
    cudaGetSymbolAddress((void**)&pAbsF, g_absF);
    cudaGetSymbolAddress((void**)&pAbsC, g_absC);
    cudaGetSymbolAddress((void**)&pAbsQ, g_absQ);
    cudaGetSymbolAddress((void**)&pAbsW, g_absW);
    cudaGetSymbolAddress((void**)&pFiT, g_FiT);
    cudaGetSymbolAddress((void**)&pCBiT, g_CBiT);
    cudaGetSymbolAddress((void**)&pQiT, g_QiT);
    cudaGetSymbolAddress((void**)&pWih8T, g_Wih8T);

    static bool attr_done = false;
    if (!attr_done) {
        cudaFuncSetAttribute(gru_kernel, cudaFuncAttributeMaxDynamicSharedMemorySize,
                             64*K3*4);
        attr_done = true;
    }

    dim3 tb(32, 8);

    init_misc<<<(M_+255)/256, 256>>>();                                   // 0
    prep_wct<<<(K3*DCB+255)/256, 256>>>(conv_w);                          // 1
    transpose_f<<<dim3(DIN/32, HMID/32), tb>>>(w1, pW1t, HMID, DIN);      // 2
    gemm_tn<1><<<dim3(HMID/BN, M_/BM), 256>>>(x, pW1t, b1, pY1, M_, HMID, DIN); // 3 <- ncu
    transpose_f<<<dim3(HMID/32, DCB/32), tb>>>(w2, pW2t, DCB, HMID);
    gemm_tn<1><<<dim3(DCB/BN,  M_/BM), 256>>>(pY1, pW2t, b2, pY2, M_, DCB, HMID);
    gemm_conv<<<dim3(DCB/BN, M_/BM), 256>>>(pY2, pWct, conv_b, pF);

    cnorm_k<<<KCB/256, 256>>>(cb);
    rownorm_k<<<M_/256, 256>>>();
    quant_pack<<<M_/32, 256>>>(pF, pAbsF, pFiT, M_);
    quant_pack<<<KCB/32, 256>>>(cb, pAbsC, pCBiT, KCB);
    absmax_rows<<<K3, 256>>>(wih, pAbsW);
    quant_pack<<<K3/32, 256>>>(wih, pAbsW, pWih8T, K3);

    vq_i8<<<dim3(M_/128, KCB/128), 256>>>();
    vq_rescue<<<M_/8, 256>>>(cb);
    vq_extract_mse<<<M_, 256>>>(cb, out);

    quant_pack<<<M_/32, 256>>>(out + M_, pAbsQ, pQiT, M_);
    xproj_i8<<<dim3(M_/128, K3/128), 256>>>(bih);
    whh_quant<<<K3, 256>>>(whh);
    gru_kernel<<<B_, 768, 64*K3*4>>>(bhh);

    finalize_k<<<1, 1>>>(out);
}